// round 14
// baseline (speedup 1.0000x reference)
#include <cuda_runtime.h>
#include <cstdint>

// LatticeSnake: B=32, L=512, W=9. Output [B, L, 9,9,9, 1] fp32 (48 MB).
// Doubled walk coords (the 2(L-1) grid offset cancels):
//   residue j:   p = 2*idx[j],         v = acids[j]*mask[j]
//   midpoint k:  p = idx[k]+idx[k+1],  v = (acids[k]+acids[k+1]+1)*mask[k+1]
//   voxel (i,r): value = sum of points at p == 2*idx[i] + r - 4
//
// R14: sparsity-first. Output is ~97% zeros (a 9^3 window holds ~10-30 snake
// points). Per 8-window CTA:
//   fill:   zero own 23.3KB slice with STG.128 (the true 48MB floor)
//   scan:   8 LDG.128 rounds over precomputed points, bbox test,
//           warp-segmented compaction (private 256-slot segments, no atomics)
//   ONE barrier
//   pairs:  hit x 8 windows dense loop (thread owns window tid&7, center
//           offset in regs); in-window hits -> RED.ADD.F32 (duplicates sum;
//           fill-before-RED ordered by the barrier, CTA-private slice)

#define LS_L    512
#define LS_W    9
#define LS_W3   729
#define LS_R    8                // windows per K2 CTA
#define LS_NT   128
#define LS_NG   (LS_L / LS_R)    // 64 groups per batch
#define LS_MP   1024             // padded point count per batch

__device__ int4 g_points[64 * LS_MP];        // px,py,pz,value_bits
__device__ int  g_meta[64 * LS_NG * 16];     // bb(6), pad(2), wOff[8] packed

// ---------------- Kernel 1: points + per-group meta ----------------
__global__ __launch_bounds__(512)
void ls_prep_kernel(const float* __restrict__ acids,
                    const float* __restrict__ mask,
                    const int*   __restrict__ idx)
{
    __shared__ alignas(16) int   sidx[LS_L * 3];
    __shared__ alignas(16) float sA[LS_L];
    __shared__ alignas(16) float sM[LS_L];

    const int b   = blockIdx.x;
    const int tid = threadIdx.x;
    const int*   gi = idx   + (size_t)b * LS_L * 3;
    const float* ga = acids + (size_t)b * LS_L;
    const float* gm = mask  + (size_t)b * LS_L;

    {
        const int4* gi4 = reinterpret_cast<const int4*>(gi);
        int4* s4 = reinterpret_cast<int4*>(sidx);
        for (int e = tid; e < (LS_L * 3) / 4; e += 512) s4[e] = gi4[e];
        const float4* ga4 = reinterpret_cast<const float4*>(ga);
        const float4* gm4 = reinterpret_cast<const float4*>(gm);
        float4* a4 = reinterpret_cast<float4*>(sA);
        float4* m4 = reinterpret_cast<float4*>(sM);
        if (tid < LS_L / 4) { a4[tid] = ga4[tid]; m4[tid] = gm4[tid]; }
    }
    __syncthreads();

    int4* gp = g_points + b * LS_MP;

    // residues
    {
        const int jj = 3 * tid;
        gp[tid] = make_int4(2 * sidx[jj + 0], 2 * sidx[jj + 1],
                            2 * sidx[jj + 2],
                            __float_as_int(sA[tid] * sM[tid]));
    }
    // midpoints + sentinel at slot 1023
    {
        const int j = tid + LS_L;
        if (tid < LS_L - 1) {
            const int jj = 3 * tid;
            gp[j] = make_int4(sidx[jj + 0] + sidx[jj + 3],
                              sidx[jj + 1] + sidx[jj + 4],
                              sidx[jj + 2] + sidx[jj + 5],
                              __float_as_int((sA[tid] + sA[tid + 1] + 1.0f)
                                             * sM[tid + 1]));
        } else if (tid == LS_L - 1) {
            gp[j] = make_int4(1 << 28, 1 << 28, 1 << 28, 0);  // sentinel
        }
    }

    // per-group meta: thread = (group g = tid>>3, window r = tid&7)
    {
        const int g  = tid >> 3;
        const int r  = tid & 7;
        const int jj = 3 * (g * LS_R + r);
        const int cx = 2 * sidx[jj + 0];
        const int cy = 2 * sidx[jj + 1];
        const int cz = 2 * sidx[jj + 2];
        int xmin = cx, xmax = cx, ymin = cy, ymax = cy, zmin = cz, zmax = cz;
        #pragma unroll
        for (int d = 4; d >= 1; d >>= 1) {   // segmented reduce over 8 lanes
            xmin = min(xmin, __shfl_xor_sync(0xffffffffu, xmin, d));
            xmax = max(xmax, __shfl_xor_sync(0xffffffffu, xmax, d));
            ymin = min(ymin, __shfl_xor_sync(0xffffffffu, ymin, d));
            ymax = max(ymax, __shfl_xor_sync(0xffffffffu, ymax, d));
            zmin = min(zmin, __shfl_xor_sync(0xffffffffu, zmin, d));
            zmax = max(zmax, __shfl_xor_sync(0xffffffffu, zmax, d));
        }
        int* m = g_meta + (b * LS_NG + g) * 16;
        // window-center offset relative to bbox min, packed bytes
        m[8 + r] = ((cx - xmin) << 16) | ((cy - ymin) << 8) | (cz - zmin);
        if (r == 0) {
            m[0] = xmin - 4; m[1] = ymin - 4; m[2] = zmin - 4;
            m[3] = xmax - xmin + 9;
            m[4] = ymax - ymin + 9;
            m[5] = zmax - zmin + 9;
        }
    }
}

// ---------------- Kernel 2: fill + compact + sparse scatter ----------------
__global__ __launch_bounds__(LS_NT, 14)
void lattice_snake_kernel(float* __restrict__ out)
{
    __shared__ alignas(16) int2 sHits[4 * 256];   // 4 warp segments, 8 KB
    __shared__ int sCnt[4];

    const int b    = blockIdx.x >> 6;            // / LS_NG
    const int g    = blockIdx.x & (LS_NG - 1);
    const int tid  = threadIdx.x;
    const int wrp  = tid >> 5;
    const int lane = tid & 31;

    const int4* gp = g_points + b * LS_MP;
    const int*  mt = g_meta + (b * LS_NG + g) * 16;
    float* gout = out + (size_t)(b * LS_L + g * LS_R) * LS_W3;

    // ---- fill: zero own slice, STG.128 (1458 float4) ----
    {
        float4* o4 = reinterpret_cast<float4*>(gout);
        const float4 z = make_float4(0.f, 0.f, 0.f, 0.f);
        for (int e = tid; e < (LS_R * LS_W3) / 4; e += LS_NT) o4[e] = z;
    }

    // ---- meta to registers (broadcast LDGs, L2-hot) ----
    const int gxl = mt[0], gyl = mt[1], gzl = mt[2];
    const int sx  = mt[3], sy  = mt[4], sz  = mt[5];
    const int wl  = tid & 7;                     // this thread's window
    const int wo  = mt[8 + wl];
    const unsigned cox = (unsigned)(wo >> 16);
    const unsigned coy = (unsigned)((wo >> 8) & 255);
    const unsigned coz = (unsigned)(wo & 255);
    float* wout = gout + wl * LS_W3;

    // ---- scan 1024 points; warp-segmented ballot compaction ----
    int cnt = 0;
    #pragma unroll
    for (int rnd = 0; rnd < LS_MP / LS_NT; rnd++) {
        const int4 p = gp[rnd * LS_NT + tid];
        const unsigned ux = (unsigned)(p.x - gxl);
        const unsigned uy = (unsigned)(p.y - gyl);
        const unsigned uz = (unsigned)(p.z - gzl);
        const bool hit = (ux < (unsigned)sx) & (uy < (unsigned)sy)
                       & (uz < (unsigned)sz);
        const unsigned m = __ballot_sync(0xffffffffu, hit);
        if (hit) {
            const int pos = wrp * 256 + cnt
                          + __popc(m & ((1u << lane) - 1u));
            sHits[pos] = make_int2((int)((ux << 16) | (uy << 8) | uz), p.w);
        }
        cnt += __popc(m);
    }
    if (lane == 0) sCnt[wrp] = cnt;
    __syncthreads();   // hits visible; fill STGs ordered before REDs

    // ---- pairs: hit x 8 windows; in-window -> RED.ADD.F32 ----
    #pragma unroll
    for (int seg = 0; seg < 4; seg++) {
        const int nP = sCnt[seg] * 8;
        for (int t = tid; t < nP; t += LS_NT) {
            const int2 hv = sHits[seg * 256 + (t >> 3)];  // t&7 == wl
            const unsigned h = (unsigned)hv.x;
            const unsigned rx = (h >> 16)        - cox;
            const unsigned ry = ((h >> 8) & 255u) - coy;
            const unsigned rz = (h & 255u)        - coz;
            if (max(rx, max(ry, rz)) <= 8u) {
                const int lin = (int)((rx * LS_W + ry) * LS_W + rz);
                atomicAdd(&wout[lin], __int_as_float(hv.y));   // RED.ADD
            }
        }
    }
}

extern "C" void kernel_launch(void* const* d_in, const int* in_sizes, int n_in,
                              void* d_out, int out_size)
{
    const float* acids = (const float*)d_in[0];   // [B, L]
    const float* mask  = (const float*)d_in[1];   // [B, L]
    const int*   idx   = (const int*)  d_in[2];   // [B, L, 3]
    float*       out   = (float*)d_out;           // [B, L, 9,9,9, 1]

    const int nB = in_sizes[0] / LS_L;            // 32
    ls_prep_kernel<<<nB, 512>>>(acids, mask, idx);
    lattice_snake_kernel<<<nB * LS_NG, LS_NT>>>(out);
}

// round 15
// speedup vs baseline: 1.1921x; 1.1921x over previous
#include <cuda_runtime.h>
#include <cstdint>

// LatticeSnake: B=32, L=512, W=9. Output [B, L, 9,9,9, 1] fp32 (48 MB).
// Doubled walk coords (the 2(L-1) grid offset cancels):
//   residue j:   p = 2*idx[j],         v = acids[j]*mask[j]
//   midpoint k:  p = idx[k]+idx[k+1],  v = (acids[k]+acids[k+1]+1)*mask[k+1]
//   voxel (i,r): value = sum of points at p == 2*idx[i] + r - 4
//
// R15 = R12 (best K2, 14.37us: dense grid-gather, R=8, NT=128) + PDL:
//   K2 launches with programmaticStreamSerialization; zeroes its smem grid
//   (K1-independent), then griddepcontrol.wait before reading K1's scratch.
//   K1 signals griddepcontrol.launch_dependents after its stores.
//   Kills the ~2.5us K1+launch-gap that was 15% of wallclock.

#define LS_L    512
#define LS_W    9
#define LS_W3   729
#define LS_R    8                // windows per K2 CTA
#define LS_NT   128
#define LS_NG   (LS_L / LS_R)    // 64 groups per batch
#define LS_MP   1024             // padded point count per batch
#define GRID_F  2560             // >= worst-case vol 15*13*13 = 2535

__device__ int4 g_points[64 * LS_MP];        // px,py,pz,value_bits
__device__ int  g_meta[64 * LS_NG * 16];     // per group: bbox(6) + base[8]

// ---------------- Kernel 1: points + per-group meta ----------------
__global__ __launch_bounds__(512)
void ls_prep_kernel(const float* __restrict__ acids,
                    const float* __restrict__ mask,
                    const int*   __restrict__ idx)
{
    __shared__ alignas(16) int   sidx[LS_L * 3];
    __shared__ alignas(16) float sA[LS_L];
    __shared__ alignas(16) float sM[LS_L];

    const int b   = blockIdx.x;
    const int tid = threadIdx.x;
    const int*   gi = idx   + (size_t)b * LS_L * 3;
    const float* ga = acids + (size_t)b * LS_L;
    const float* gm = mask  + (size_t)b * LS_L;

    {
        const int4* gi4 = reinterpret_cast<const int4*>(gi);
        int4* s4 = reinterpret_cast<int4*>(sidx);
        for (int e = tid; e < (LS_L * 3) / 4; e += 512) s4[e] = gi4[e];
        const float4* ga4 = reinterpret_cast<const float4*>(ga);
        const float4* gm4 = reinterpret_cast<const float4*>(gm);
        float4* a4 = reinterpret_cast<float4*>(sA);
        float4* m4 = reinterpret_cast<float4*>(sM);
        if (tid < LS_L / 4) { a4[tid] = ga4[tid]; m4[tid] = gm4[tid]; }
    }
    __syncthreads();

    int4* gp = g_points + b * LS_MP;

    // residues (j = tid)
    {
        const int jj = 3 * tid;
        gp[tid] = make_int4(2 * sidx[jj + 0], 2 * sidx[jj + 1],
                            2 * sidx[jj + 2],
                            __float_as_int(sA[tid] * sM[tid]));
    }
    // midpoints (k = tid) + sentinel at slot 1023
    {
        const int j = tid + LS_L;
        if (tid < LS_L - 1) {
            const int jj = 3 * tid;
            gp[j] = make_int4(sidx[jj + 0] + sidx[jj + 3],
                              sidx[jj + 1] + sidx[jj + 4],
                              sidx[jj + 2] + sidx[jj + 5],
                              __float_as_int((sA[tid] + sA[tid + 1] + 1.0f)
                                             * sM[tid + 1]));
        } else if (tid == LS_L - 1) {
            gp[j] = make_int4(1 << 28, 1 << 28, 1 << 28, 0);  // sentinel
        }
    }

    // per-group meta: thread = (group g = tid>>3, window r = tid&7)
    {
        const int g  = tid >> 3;
        const int r  = tid & 7;
        const int jj = 3 * (g * LS_R + r);
        const int cx = 2 * sidx[jj + 0];
        const int cy = 2 * sidx[jj + 1];
        const int cz = 2 * sidx[jj + 2];
        int xmin = cx, xmax = cx, ymin = cy, ymax = cy, zmin = cz, zmax = cz;
        #pragma unroll
        for (int d = 4; d >= 1; d >>= 1) {   // segmented reduce over 8 lanes
            xmin = min(xmin, __shfl_xor_sync(0xffffffffu, xmin, d));
            xmax = max(xmax, __shfl_xor_sync(0xffffffffu, xmax, d));
            ymin = min(ymin, __shfl_xor_sync(0xffffffffu, ymin, d));
            ymax = max(ymax, __shfl_xor_sync(0xffffffffu, ymax, d));
            zmin = min(zmin, __shfl_xor_sync(0xffffffffu, zmin, d));
            zmax = max(zmax, __shfl_xor_sync(0xffffffffu, zmax, d));
        }
        const int syv = ymax - ymin + 9;
        const int szv = zmax - zmin + 9;
        int* m = g_meta + (b * LS_NG + g) * 16;
        m[6 + r] = ((cx - xmin) * syv + (cy - ymin)) * szv + (cz - zmin);
        if (r == 0) {
            m[0] = xmin - 4; m[1] = ymin - 4; m[2] = zmin - 4;
            m[3] = xmax - xmin + 9; m[4] = syv; m[5] = szv;
        }
    }

    // PDL: scratch written -> let dependent grid's wait proceed
    asm volatile("griddepcontrol.launch_dependents;" ::: "memory");
}

// ---------------- Kernel 2: main (grid gather) ----------------
__global__ __launch_bounds__(LS_NT, 16)
void lattice_snake_kernel(float* __restrict__ out)
{
    __shared__ alignas(16) float grid[GRID_F];   // 10240 B
    __shared__ int sMeta[16];                    // bbox(6) + base[8]

    const int b   = blockIdx.x >> 6;            // / LS_NG
    const int g   = blockIdx.x & (LS_NG - 1);
    const int tid = threadIdx.x;

    const int4* gp = g_points + b * LS_MP;
    float* gout = out + (size_t)(b * LS_L + g * LS_R) * LS_W3;

    // ---- zero grid (640 float4) -- independent of K1, overlaps it ----
    {
        float4* g4 = reinterpret_cast<float4*>(grid);
        const float4 z = make_float4(0.f, 0.f, 0.f, 0.f);
        #pragma unroll
        for (int e = tid; e < GRID_F / 4; e += LS_NT) g4[e] = z;
    }

    // PDL: wait for K1's scratch to be visible
    asm volatile("griddepcontrol.wait;" ::: "memory");

    // meta load (after wait)
    if (tid < 14) sMeta[tid] = g_meta[(b * LS_NG + g) * 16 + tid];
    __syncthreads();

    const int gxl = sMeta[0], gyl = sMeta[1], gzl = sMeta[2];
    const int sx  = sMeta[3], sy  = sMeta[4], sz  = sMeta[5];

    // ---- scan 1024 packed points; 8 coalesced LDG.128 rounds (MLP 8) ----
    #pragma unroll
    for (int rnd = 0; rnd < LS_MP / LS_NT; rnd++) {
        const int4 p = gp[rnd * LS_NT + tid];
        const unsigned ux = (unsigned)(p.x - gxl);
        const unsigned uy = (unsigned)(p.y - gyl);
        const unsigned uz = (unsigned)(p.z - gzl);
        if (ux < (unsigned)sx && uy < (unsigned)sy && uz < (unsigned)sz)
            atomicAdd(&grid[(ux * sy + uy) * sz + uz], __int_as_float(p.w));
    }

    // per-thread voxel decomposition (6 rounds of 128 cover 729)
    int ro[6];
    #pragma unroll
    for (int k = 0; k < 6; k++) {
        const int lin = tid + k * LS_NT;
        const int rx  = lin / 81;
        const int rem = lin - rx * 81;
        const int ry  = rem / 9;
        const int rz  = rem - ry * 9;
        ro[k] = (rx * sy + ry) * sz + rz;
    }
    __syncthreads();   // grid complete

    // ---- gather: voxel = one LDS + one coalesced STG.32 ----
    const bool k5ok = tid < (LS_W3 - 5 * LS_NT);   // 89
    #pragma unroll
    for (int w = 0; w < LS_R; w++) {
        const int Aw = sMeta[6 + w];               // broadcast LDS
        float* gw = gout + w * LS_W3;
        gw[tid]              = grid[Aw + ro[0]];
        gw[tid + 1 * LS_NT]  = grid[Aw + ro[1]];
        gw[tid + 2 * LS_NT]  = grid[Aw + ro[2]];
        gw[tid + 3 * LS_NT]  = grid[Aw + ro[3]];
        gw[tid + 4 * LS_NT]  = grid[Aw + ro[4]];
        if (k5ok) gw[tid + 5 * LS_NT] = grid[Aw + ro[5]];
    }
}

extern "C" void kernel_launch(void* const* d_in, const int* in_sizes, int n_in,
                              void* d_out, int out_size)
{
    const float* acids = (const float*)d_in[0];   // [B, L]
    const float* mask  = (const float*)d_in[1];   // [B, L]
    const int*   idx   = (const int*)  d_in[2];   // [B, L, 3]
    float*       out   = (float*)d_out;           // [B, L, 9,9,9, 1]

    const int nB = in_sizes[0] / LS_L;            // 32

    // K1: normal launch (default stream)
    ls_prep_kernel<<<nB, 512>>>(acids, mask, idx);

    // K2: PDL launch -- overlaps its prologue with K1 / launch latency
    cudaLaunchConfig_t cfg = {};
    cfg.gridDim  = dim3(nB * LS_NG);
    cfg.blockDim = dim3(LS_NT);
    cfg.dynamicSmemBytes = 0;
    cfg.stream = 0;   // legacy default stream (same as <<<>>> above)
    cudaLaunchAttribute attrs[1];
    attrs[0].id = cudaLaunchAttributeProgrammaticStreamSerialization;
    attrs[0].val.programmaticStreamSerializationAllowed = 1;
    cfg.attrs = attrs;
    cfg.numAttrs = 1;
    cudaLaunchKernelEx(&cfg, lattice_snake_kernel, out);
}